// round 4
// baseline (speedup 1.0000x reference)
#include <cuda_runtime.h>
#include <cstdint>

#define IN_FEAT 256
#define OUT_FEAT 128

typedef unsigned long long ull;

// packed f32x2 fma: d = a*b + c  (elementwise on 2 packed floats)
__device__ __forceinline__ ull fma2(ull a, ull b, ull c) {
    ull d;
    asm("fma.rn.f32x2 %0, %1, %2, %3;" : "=l"(d) : "l"(a), "l"(b), "l"(c));
    return d;
}

union F4U2 {
    float4 f;
    ull    u[2];
};

// ---------------------------------------------------------------------------
// GEMM: C[M,128] = A[M,256] * B[256,128]  via packed f32x2 FMA.
// BM=128, BN=128, BK=16, 256 threads; 8 rows x 8 cols per thread,
// rows paired into f32x2 lanes (4 row-pairs x 8 cols = 32 FFMA2 / k).
// ---------------------------------------------------------------------------
#define BM 128
#define BK 16

__global__ __launch_bounds__(256) void gemm_kernel(
    const float* __restrict__ A,   // [M, 256]
    const float* __restrict__ B,   // [256, 128]
    float* __restrict__ C,         // [M, 128]
    int M)
{
    __shared__ float  Ask[BK][BM + 4];        // transposed A tile (rows contiguous)
    __shared__ float2 Bdup[BK][OUT_FEAT];     // B value duplicated into both lanes

    const int tid = threadIdx.x;
    const int m0  = blockIdx.x * BM;
    const int tx  = tid & 15;    // col group: cols tx*8 .. tx*8+7
    const int ty  = tid >> 4;    // row group: rows ty*8 .. ty*8+7

    ull acc2[4][8];              // [row-pair][col]
#pragma unroll
    for (int p = 0; p < 4; p++)
#pragma unroll
        for (int j = 0; j < 8; j++) acc2[p][j] = 0ull;

    for (int k0 = 0; k0 < IN_FEAT; k0 += BK) {
        // --- load A tile (128 rows x 16 k) transposed into smem ---
#pragma unroll
        for (int t = 0; t < 2; t++) {
            int id  = tid + t * 256;     // 0..511 float4 ids
            int row = id >> 2;           // 0..127
            int kp  = (id & 3) * 4;      // 0,4,8,12
            float4 a;
            int gr = m0 + row;
            if (gr < M) {
                a = *reinterpret_cast<const float4*>(A + (size_t)gr * IN_FEAT + k0 + kp);
            } else {
                a = make_float4(0.f, 0.f, 0.f, 0.f);
            }
            Ask[kp + 0][row] = a.x;
            Ask[kp + 1][row] = a.y;
            Ask[kp + 2][row] = a.z;
            Ask[kp + 3][row] = a.w;
        }
        // --- load B tile (16 x 128), duplicating each value into a float2 ---
#pragma unroll
        for (int t = 0; t < 8; t++) {
            int id  = tid + t * 256;     // 0..2047
            int k   = id >> 7;
            int col = id & 127;
            float bv = B[(k0 + k) * OUT_FEAT + col];
            Bdup[k][col] = make_float2(bv, bv);
        }
        __syncthreads();

#pragma unroll
        for (int k = 0; k < BK; k++) {
            F4U2 a01, a23;
            a01.f = *reinterpret_cast<float4*>(&Ask[k][ty * 8]);
            a23.f = *reinterpret_cast<float4*>(&Ask[k][ty * 8 + 4]);
            ull a2[4] = {a01.u[0], a01.u[1], a23.u[0], a23.u[1]};

            F4U2 b0, b1, b2, b3;
            b0.f = *reinterpret_cast<float4*>(&Bdup[k][tx * 8 + 0]);
            b1.f = *reinterpret_cast<float4*>(&Bdup[k][tx * 8 + 2]);
            b2.f = *reinterpret_cast<float4*>(&Bdup[k][tx * 8 + 4]);
            b3.f = *reinterpret_cast<float4*>(&Bdup[k][tx * 8 + 6]);
            ull bd[8] = {b0.u[0], b0.u[1], b1.u[0], b1.u[1],
                         b2.u[0], b2.u[1], b3.u[0], b3.u[1]};

#pragma unroll
            for (int p = 0; p < 4; p++)
#pragma unroll
                for (int j = 0; j < 8; j++)
                    acc2[p][j] = fma2(a2[p], bd[j], acc2[p][j]);
        }
        __syncthreads();
    }

    // --- epilogue: unpack row-pairs and store ---
#pragma unroll
    for (int p = 0; p < 4; p++) {
        int r0 = m0 + ty * 8 + 2 * p;
        float lo[8], hi[8];
#pragma unroll
        for (int j = 0; j < 8; j++) {
            ull v = acc2[p][j];
            lo[j] = __int_as_float((int)(v & 0xffffffffull));
            hi[j] = __int_as_float((int)(v >> 32));
        }
        if (r0 < M) {
            float* cp = C + (size_t)r0 * OUT_FEAT + tx * 8;
            *reinterpret_cast<float4*>(cp)     = make_float4(lo[0], lo[1], lo[2], lo[3]);
            *reinterpret_cast<float4*>(cp + 4) = make_float4(lo[4], lo[5], lo[6], lo[7]);
        }
        if (r0 + 1 < M) {
            float* cp = C + (size_t)(r0 + 1) * OUT_FEAT + tx * 8;
            *reinterpret_cast<float4*>(cp)     = make_float4(hi[0], hi[1], hi[2], hi[3]);
            *reinterpret_cast<float4*>(cp + 4) = make_float4(hi[4], hi[5], hi[6], hi[7]);
        }
    }
}

// ---------------------------------------------------------------------------
// SPMM, sorted edge_row. One WARP per chunk of 512 edges; each lane covers
// 4 output columns (32 lanes x float4 = 128 cols). Segmented reduction in
// registers; boundary segments via atomicAdd (x pre-zeroed).
// ---------------------------------------------------------------------------
#define SP_THREADS 256
#define SP_WARPS   8
#define SP_WCHUNK  512
#define SP_BCHUNK  (SP_WARPS * SP_WCHUNK)   // 4096 edges per block

__global__ __launch_bounds__(SP_THREADS) void spmm_kernel(
    const int*   __restrict__ erow,
    const int*   __restrict__ ecol,
    const float* __restrict__ eval,
    const float* __restrict__ femb,   // [N, 128]
    float*       __restrict__ x,      // [N, 128], pre-zeroed
    int E)
{
    __shared__ int   srow[SP_BCHUNK];
    __shared__ int   scol[SP_BCHUNK];
    __shared__ float sval[SP_BCHUNK];

    const int base   = blockIdx.x * SP_BCHUNK;
    const int navail = min(SP_BCHUNK, E - base);

    for (int i = threadIdx.x; i < navail; i += SP_THREADS) {
        srow[i] = erow[base + i];
        scol[i] = ecol[base + i];
        sval[i] = eval[base + i];
    }
    __syncthreads();

    const int warp = threadIdx.x >> 5;
    const int lane = threadIdx.x & 31;
    const int ws   = warp * SP_WCHUNK;
    if (ws >= navail) return;
    const int we   = min(ws + SP_WCHUNK, navail);
    const int coff = lane * 4;                 // this lane's 4 columns

    float4 acc = make_float4(0.f, 0.f, 0.f, 0.f);
    int  cur   = srow[ws];
    bool first = true;

    for (int i = ws; i < we; i += 4) {
        const int cnt = we - i;                // >=1
        float4 v[4];
        // prefetch up to 4 gathers (MLP=4, LDG.128 each)
#pragma unroll
        for (int j = 0; j < 4; j++)
            if (j < cnt)
                v[j] = *reinterpret_cast<const float4*>(femb + scol[i + j] * OUT_FEAT + coff);
#pragma unroll
        for (int j = 0; j < 4; j++) {
            if (j < cnt) {
                int r = srow[i + j];
                if (r != cur) {                 // uniform across warp: no divergence
                    float* xp = x + cur * OUT_FEAT + coff;
                    if (first) {
                        atomicAdd(xp + 0, acc.x); atomicAdd(xp + 1, acc.y);
                        atomicAdd(xp + 2, acc.z); atomicAdd(xp + 3, acc.w);
                        first = false;
                    } else {
                        *reinterpret_cast<float4*>(xp) = acc;
                    }
                    acc = make_float4(0.f, 0.f, 0.f, 0.f);
                    cur = r;
                }
                float ev = sval[i + j];
                acc.x += ev * v[j].x;
                acc.y += ev * v[j].y;
                acc.z += ev * v[j].z;
                acc.w += ev * v[j].w;
            }
        }
    }
    // trailing segment may continue into the next warp's chunk
    float* xp = x + cur * OUT_FEAT + coff;
    atomicAdd(xp + 0, acc.x); atomicAdd(xp + 1, acc.y);
    atomicAdd(xp + 2, acc.z); atomicAdd(xp + 3, acc.w);
}

// ---------------------------------------------------------------------------
// Launch
// ---------------------------------------------------------------------------
extern "C" void kernel_launch(void* const* d_in, const int* in_sizes, int n_in,
                              void* d_out, int out_size)
{
    const float* feat = (const float*)d_in[0];   // [N, 256]
    const int*   erow = (const int*)  d_in[1];   // [E]
    const int*   ecol = (const int*)  d_in[2];   // [E]
    const float* eval = (const float*)d_in[3];   // [E]
    const float* W    = (const float*)d_in[4];   // [256, 128]

    const int M = in_sizes[0] / IN_FEAT;         // 100000
    const int E = in_sizes[1];                   // 3200000

    float* femb = (float*)d_out;                     // first output
    float* x    = femb + (size_t)M * OUT_FEAT;       // second output

    // zero the segment-sum output (atomics accumulate into it)
    cudaMemsetAsync(x, 0, (size_t)M * OUT_FEAT * sizeof(float), 0);

    gemm_kernel<<<(M + BM - 1) / BM, 256>>>(feat, W, femb, M);
    spmm_kernel<<<(E + SP_BCHUNK - 1) / SP_BCHUNK, SP_THREADS>>>(erow, ecol, eval, femb, x, E);
}

// round 5
// speedup vs baseline: 2.1055x; 2.1055x over previous
#include <cuda_runtime.h>
#include <cstdint>

#define IN_FEAT 256
#define OUT_FEAT 128

// ---------------------------------------------------------------------------
// GEMM: C[M,128] = A[M,256] * B[256,128]   (fp32, register-blocked SIMT)
// BM=128, BN=128, BK=16, 256 threads, 8x8 outputs/thread.  (R1 version —
// measured at the FFMA-pipe floor ~160us.)
// ---------------------------------------------------------------------------
#define BM 128
#define BK 16

__global__ __launch_bounds__(256) void gemm_kernel(
    const float* __restrict__ A,   // [M, 256]
    const float* __restrict__ B,   // [256, 128]
    float* __restrict__ C,         // [M, 128]
    int M)
{
    __shared__ float Ask[BK][BM + 4];   // transposed A tile, padded
    __shared__ float Bs[BK][OUT_FEAT];

    const int tid = threadIdx.x;
    const int m0  = blockIdx.x * BM;
    const int tx  = tid & 15;    // col group: cols tx*8 .. tx*8+7
    const int ty  = tid >> 4;    // row group: rows ty*8 .. ty*8+7

    float acc[8][8];
#pragma unroll
    for (int i = 0; i < 8; i++)
#pragma unroll
        for (int j = 0; j < 8; j++) acc[i][j] = 0.0f;

    for (int k0 = 0; k0 < IN_FEAT; k0 += BK) {
        // --- load A tile (128 rows x 16 k) transposed into smem ---
#pragma unroll
        for (int t = 0; t < 2; t++) {
            int id  = tid + t * 256;     // 0..511 float4 ids
            int row = id >> 2;           // 0..127
            int kp  = (id & 3) * 4;      // 0,4,8,12
            float4 a;
            int gr = m0 + row;
            if (gr < M) {
                a = *reinterpret_cast<const float4*>(A + (size_t)gr * IN_FEAT + k0 + kp);
            } else {
                a = make_float4(0.f, 0.f, 0.f, 0.f);
            }
            Ask[kp + 0][row] = a.x;
            Ask[kp + 1][row] = a.y;
            Ask[kp + 2][row] = a.z;
            Ask[kp + 3][row] = a.w;
        }
        // --- load B tile (16 x 128, contiguous in global) ---
        {
            const float4* Bg  = reinterpret_cast<const float4*>(B + k0 * OUT_FEAT);
            float4*       Bs4 = reinterpret_cast<float4*>(&Bs[0][0]);
            Bs4[tid]       = Bg[tid];
            Bs4[tid + 256] = Bg[tid + 256];
        }
        __syncthreads();

#pragma unroll
        for (int k = 0; k < BK; k++) {
            float4 a0 = *reinterpret_cast<float4*>(&Ask[k][ty * 8]);
            float4 a1 = *reinterpret_cast<float4*>(&Ask[k][ty * 8 + 4]);
            float4 b0 = *reinterpret_cast<float4*>(&Bs[k][tx * 8]);
            float4 b1 = *reinterpret_cast<float4*>(&Bs[k][tx * 8 + 4]);
            float ar[8] = {a0.x, a0.y, a0.z, a0.w, a1.x, a1.y, a1.z, a1.w};
            float br[8] = {b0.x, b0.y, b0.z, b0.w, b1.x, b1.y, b1.z, b1.w};
#pragma unroll
            for (int i = 0; i < 8; i++)
#pragma unroll
                for (int j = 0; j < 8; j++)
                    acc[i][j] += ar[i] * br[j];
        }
        __syncthreads();
    }

    // --- epilogue ---
#pragma unroll
    for (int i = 0; i < 8; i++) {
        int gr = m0 + ty * 8 + i;
        if (gr < M) {
            float4 o0 = make_float4(acc[i][0], acc[i][1], acc[i][2], acc[i][3]);
            float4 o1 = make_float4(acc[i][4], acc[i][5], acc[i][6], acc[i][7]);
            float* cp = C + (size_t)gr * OUT_FEAT + tx * 8;
            *reinterpret_cast<float4*>(cp)     = o0;
            *reinterpret_cast<float4*>(cp + 4) = o1;
        }
    }
}

// ---------------------------------------------------------------------------
// SPMM, sorted edge_row. One WARP per chunk of 256 edges; each lane covers
// 4 output columns (32 lanes x float4 = 128 cols). Segmented reduction in
// registers; boundary segments via atomicAdd (x pre-zeroed).
// smem staging cut to 24KB/block -> 8 blocks/SM -> 64 resident warps.
// ---------------------------------------------------------------------------
#define SP_THREADS 256
#define SP_WARPS   8
#define SP_WCHUNK  256
#define SP_BCHUNK  (SP_WARPS * SP_WCHUNK)   // 2048 edges per block

__global__ __launch_bounds__(SP_THREADS) void spmm_kernel(
    const int*   __restrict__ erow,
    const int*   __restrict__ ecol,
    const float* __restrict__ eval,
    const float* __restrict__ femb,   // [N, 128]
    float*       __restrict__ x,      // [N, 128], pre-zeroed
    int E)
{
    __shared__ int   srow[SP_BCHUNK];
    __shared__ int   scol[SP_BCHUNK];
    __shared__ float sval[SP_BCHUNK];

    const int base   = blockIdx.x * SP_BCHUNK;
    const int navail = min(SP_BCHUNK, E - base);

    for (int i = threadIdx.x; i < navail; i += SP_THREADS) {
        srow[i] = erow[base + i];
        scol[i] = ecol[base + i];
        sval[i] = eval[base + i];
    }
    __syncthreads();

    const int warp = threadIdx.x >> 5;
    const int lane = threadIdx.x & 31;
    const int ws   = warp * SP_WCHUNK;
    if (ws >= navail) return;
    const int we   = min(ws + SP_WCHUNK, navail);
    const int coff = lane * 4;                 // this lane's 4 columns

    float4 acc = make_float4(0.f, 0.f, 0.f, 0.f);
    int  cur   = srow[ws];
    bool first = true;

    for (int i = ws; i < we; i += 4) {
        const int cnt = we - i;                // >=1
        float4 v[4];
        // prefetch up to 4 gathers (MLP=4, LDG.128 each)
#pragma unroll
        for (int j = 0; j < 4; j++)
            if (j < cnt)
                v[j] = *reinterpret_cast<const float4*>(femb + scol[i + j] * OUT_FEAT + coff);
#pragma unroll
        for (int j = 0; j < 4; j++) {
            if (j < cnt) {
                int r = srow[i + j];
                if (r != cur) {                 // uniform across warp: no divergence
                    float* xp = x + cur * OUT_FEAT + coff;
                    if (first) {
                        atomicAdd(xp + 0, acc.x); atomicAdd(xp + 1, acc.y);
                        atomicAdd(xp + 2, acc.z); atomicAdd(xp + 3, acc.w);
                        first = false;
                    } else {
                        *reinterpret_cast<float4*>(xp) = acc;
                    }
                    acc = make_float4(0.f, 0.f, 0.f, 0.f);
                    cur = r;
                }
                float ev = sval[i + j];
                acc.x += ev * v[j].x;
                acc.y += ev * v[j].y;
                acc.z += ev * v[j].z;
                acc.w += ev * v[j].w;
            }
        }
    }
    // trailing segment may continue into the next warp's chunk
    float* xp = x + cur * OUT_FEAT + coff;
    atomicAdd(xp + 0, acc.x); atomicAdd(xp + 1, acc.y);
    atomicAdd(xp + 2, acc.z); atomicAdd(xp + 3, acc.w);
}

// ---------------------------------------------------------------------------
// Launch
// ---------------------------------------------------------------------------
extern "C" void kernel_launch(void* const* d_in, const int* in_sizes, int n_in,
                              void* d_out, int out_size)
{
    const float* feat = (const float*)d_in[0];   // [N, 256]
    const int*   erow = (const int*)  d_in[1];   // [E]
    const int*   ecol = (const int*)  d_in[2];   // [E]
    const float* eval = (const float*)d_in[3];   // [E]
    const float* W    = (const float*)d_in[4];   // [256, 128]

    const int M = in_sizes[0] / IN_FEAT;         // 100000
    const int E = in_sizes[1];                   // 3200000

    float* femb = (float*)d_out;                     // first output
    float* x    = femb + (size_t)M * OUT_FEAT;       // second output

    // zero the segment-sum output (atomics accumulate into it)
    cudaMemsetAsync(x, 0, (size_t)M * OUT_FEAT * sizeof(float), 0);

    gemm_kernel<<<(M + BM - 1) / BM, 256>>>(feat, W, femb, M);
    spmm_kernel<<<(E + SP_BCHUNK - 1) / SP_BCHUNK, SP_THREADS>>>(erow, ecol, eval, femb, x, E);
}

// round 13
// speedup vs baseline: 2.8022x; 1.3309x over previous
#include <cuda_runtime.h>
#include <cuda_bf16.h>
#include <cstdint>

#define IN_FEAT 256
#define OUT_FEAT 128

// ===========================================================================
// bf16 hi/lo split of fp32 (exact residual: Sterbenz)
// ===========================================================================
__device__ __forceinline__ void bf16_split(float x, unsigned short& h, unsigned short& l) {
    __nv_bfloat16 bh = __float2bfloat16(x);
    float r = x - __bfloat162float(bh);
    __nv_bfloat16 bl = __float2bfloat16(r);
    h = __bfloat16_as_ushort(bh);
    l = __bfloat16_as_ushort(bl);
}

// B pre-split, transposed to [N=128][K=256] K-major bf16 (hi & lo)
__device__ __nv_bfloat16 g_Bth[OUT_FEAT * IN_FEAT];
__device__ __nv_bfloat16 g_Btl[OUT_FEAT * IN_FEAT];

__global__ void bconv_kernel(const float* __restrict__ B) {
    int idx = blockIdx.x * blockDim.x + threadIdx.x;
    if (idx < IN_FEAT * OUT_FEAT) {
        int k = idx >> 7;        // 0..255
        int n = idx & 127;       // 0..127
        unsigned short h, l;
        bf16_split(B[idx], h, l);
        g_Bth[n * IN_FEAT + k] = __ushort_as_bfloat16(h);
        g_Btl[n * IN_FEAT + k] = __ushort_as_bfloat16(l);
    }
}

// ===========================================================================
// warp-level bf16 MMA  (m16n8k16, fp32 accum) — plain sm_80+ PTX, no 'a' target
// ===========================================================================
__device__ __forceinline__ void mma_bf16(float* c,
                                         uint32_t a0, uint32_t a1, uint32_t a2, uint32_t a3,
                                         uint32_t b0, uint32_t b1) {
    asm volatile(
        "mma.sync.aligned.m16n8k16.row.col.f32.bf16.bf16.f32 "
        "{%0,%1,%2,%3}, {%4,%5,%6,%7}, {%8,%9}, {%0,%1,%2,%3};"
        : "+f"(c[0]), "+f"(c[1]), "+f"(c[2]), "+f"(c[3])
        : "r"(a0), "r"(a1), "r"(a2), "r"(a3), "r"(b0), "r"(b1));
}

// ===========================================================================
// GEMM: C[M,128] = A[M,256] * B[256,128] via 3x bf16-split HMMA.
// 256 threads (8 warps, 4x2), BM=128, BN=128, BK=32. Register-prefetched
// gmem loads; A split in-flight; B from pre-split device arrays.
// ===========================================================================
#define GK      32                       // BK in elements
#define GSTRIDE 40                       // smem row stride in bf16 (32 + 8 pad)

__global__ __launch_bounds__(256, 1) void gemm_mma_kernel(
    const float* __restrict__ A,   // [M, 256]
    float* __restrict__ C,         // [M, 128]
    int M)
{
    __shared__ __nv_bfloat16 sAh[128 * GSTRIDE];
    __shared__ __nv_bfloat16 sAl[128 * GSTRIDE];
    __shared__ __nv_bfloat16 sBh[128 * GSTRIDE];
    __shared__ __nv_bfloat16 sBl[128 * GSTRIDE];

    const int tid  = threadIdx.x;
    const int warp = tid >> 5;
    const int lane = tid & 31;
    const int wm   = warp >> 1;          // 0..3 : 32-row strip
    const int wn   = warp & 1;           // 0..1 : 64-col strip
    const int g    = lane >> 2;          // group 0..7
    const int tig  = lane & 3;           // thread-in-group
    const int m0   = blockIdx.x * 128;

    float acc[2][8][4];                  // [mtile][ntile][frag]
#pragma unroll
    for (int t = 0; t < 2; t++)
#pragma unroll
        for (int u = 0; u < 8; u++)
#pragma unroll
            for (int q = 0; q < 4; q++) acc[t][u][q] = 0.0f;

    float4 pA[4];
    uint4  pBh[2], pBl[2];

    // ---- prefetch helpers (kb = K-chunk index, 0..7) ----
    auto loadA = [&](int kb) {
#pragma unroll
        for (int i = 0; i < 4; i++) {
            int id  = tid + i * 256;         // 0..1023
            int row = id >> 3;               // 0..127
            int u   = id & 7;                // 16B unit
            int gr  = m0 + row;
            pA[i] = (gr < M)
                ? *reinterpret_cast<const float4*>(A + (size_t)gr * IN_FEAT + kb * GK + u * 4)
                : make_float4(0.f, 0.f, 0.f, 0.f);
        }
    };
    auto loadB = [&](int kb) {
#pragma unroll
        for (int i = 0; i < 2; i++) {
            int id = tid + i * 256;          // 0..511
            int n  = id >> 2;                // 0..127
            int q  = id & 3;                 // 8-bf16 unit
            pBh[i] = *reinterpret_cast<const uint4*>(&g_Bth[n * IN_FEAT + kb * GK + q * 8]);
            pBl[i] = *reinterpret_cast<const uint4*>(&g_Btl[n * IN_FEAT + kb * GK + q * 8]);
        }
    };

    loadA(0); loadB(0);

    for (int kb = 0; kb < 8; kb++) {
        // ---- store prefetched tile to smem (A split on the fly) ----
#pragma unroll
        for (int i = 0; i < 4; i++) {
            int id  = tid + i * 256;
            int row = id >> 3;
            int u   = id & 7;
            unsigned short h0, h1, h2, h3, l0, l1, l2, l3;
            bf16_split(pA[i].x, h0, l0); bf16_split(pA[i].y, h1, l1);
            bf16_split(pA[i].z, h2, l2); bf16_split(pA[i].w, h3, l3);
            uint2 vh, vl;
            vh.x = (uint32_t)h0 | ((uint32_t)h1 << 16);
            vh.y = (uint32_t)h2 | ((uint32_t)h3 << 16);
            vl.x = (uint32_t)l0 | ((uint32_t)l1 << 16);
            vl.y = (uint32_t)l2 | ((uint32_t)l3 << 16);
            *reinterpret_cast<uint2*>(&sAh[row * GSTRIDE + u * 4]) = vh;
            *reinterpret_cast<uint2*>(&sAl[row * GSTRIDE + u * 4]) = vl;
        }
#pragma unroll
        for (int i = 0; i < 2; i++) {
            int id = tid + i * 256;
            int n  = id >> 2;
            int q  = id & 3;
            *reinterpret_cast<uint4*>(&sBh[n * GSTRIDE + q * 8]) = pBh[i];
            *reinterpret_cast<uint4*>(&sBl[n * GSTRIDE + q * 8]) = pBl[i];
        }
        __syncthreads();

        // ---- prefetch next tile while computing this one ----
        if (kb < 7) { loadA(kb + 1); loadB(kb + 1); }

        // ---- compute: 2 k16 steps ----
#pragma unroll
        for (int ks = 0; ks < 2; ks++) {
            const int kof = ks * 16 + tig * 2;
            // A fragments (hi & lo) for both 16-row tiles
            uint32_t ah[2][4], al[2][4];
#pragma unroll
            for (int t = 0; t < 2; t++) {
                int r0 = (wm * 32 + t * 16 + g) * GSTRIDE + kof;
                int r1 = r0 + 8 * GSTRIDE;
                ah[t][0] = *reinterpret_cast<uint32_t*>(&sAh[r0]);
                ah[t][1] = *reinterpret_cast<uint32_t*>(&sAh[r1]);
                ah[t][2] = *reinterpret_cast<uint32_t*>(&sAh[r0 + 8]);
                ah[t][3] = *reinterpret_cast<uint32_t*>(&sAh[r1 + 8]);
                al[t][0] = *reinterpret_cast<uint32_t*>(&sAl[r0]);
                al[t][1] = *reinterpret_cast<uint32_t*>(&sAl[r1]);
                al[t][2] = *reinterpret_cast<uint32_t*>(&sAl[r0 + 8]);
                al[t][3] = *reinterpret_cast<uint32_t*>(&sAl[r1 + 8]);
            }
#pragma unroll
            for (int u = 0; u < 8; u++) {
                int nb = (wn * 64 + u * 8 + g) * GSTRIDE + kof;
                uint32_t bh0 = *reinterpret_cast<uint32_t*>(&sBh[nb]);
                uint32_t bh1 = *reinterpret_cast<uint32_t*>(&sBh[nb + 8]);
                uint32_t bl0 = *reinterpret_cast<uint32_t*>(&sBl[nb]);
                uint32_t bl1 = *reinterpret_cast<uint32_t*>(&sBl[nb + 8]);
#pragma unroll
                for (int t = 0; t < 2; t++) {
                    mma_bf16(acc[t][u], ah[t][0], ah[t][1], ah[t][2], ah[t][3], bh0, bh1);
                    mma_bf16(acc[t][u], ah[t][0], ah[t][1], ah[t][2], ah[t][3], bl0, bl1);
                    mma_bf16(acc[t][u], al[t][0], al[t][1], al[t][2], al[t][3], bh0, bh1);
                }
            }
        }
        __syncthreads();
    }

    // ---- epilogue: fragment layout c0,c1 -> (row g), c2,c3 -> (row g+8) ----
#pragma unroll
    for (int t = 0; t < 2; t++) {
        int row0 = m0 + wm * 32 + t * 16 + g;
        int row1 = row0 + 8;
#pragma unroll
        for (int u = 0; u < 8; u++) {
            int col = wn * 64 + u * 8 + tig * 2;
            if (row0 < M)
                *reinterpret_cast<float2*>(C + (size_t)row0 * OUT_FEAT + col) =
                    make_float2(acc[t][u][0], acc[t][u][1]);
            if (row1 < M)
                *reinterpret_cast<float2*>(C + (size_t)row1 * OUT_FEAT + col) =
                    make_float2(acc[t][u][2], acc[t][u][3]);
        }
    }
}

// ---------------------------------------------------------------------------
// SPMM, sorted edge_row (unchanged from R5 — 119.8us).
// ---------------------------------------------------------------------------
#define SP_THREADS 256
#define SP_WARPS   8
#define SP_WCHUNK  256
#define SP_BCHUNK  (SP_WARPS * SP_WCHUNK)   // 2048 edges per block

__global__ __launch_bounds__(SP_THREADS) void spmm_kernel(
    const int*   __restrict__ erow,
    const int*   __restrict__ ecol,
    const float* __restrict__ eval,
    const float* __restrict__ femb,   // [N, 128]
    float*       __restrict__ x,      // [N, 128], pre-zeroed
    int E)
{
    __shared__ int   srow[SP_BCHUNK];
    __shared__ int   scol[SP_BCHUNK];
    __shared__ float sval[SP_BCHUNK];

    const int base   = blockIdx.x * SP_BCHUNK;
    const int navail = min(SP_BCHUNK, E - base);

    for (int i = threadIdx.x; i < navail; i += SP_THREADS) {
        srow[i] = erow[base + i];
        scol[i] = ecol[base + i];
        sval[i] = eval[base + i];
    }
    __syncthreads();

    const int warp = threadIdx.x >> 5;
    const int lane = threadIdx.x & 31;
    const int ws   = warp * SP_WCHUNK;
    if (ws >= navail) return;
    const int we   = min(ws + SP_WCHUNK, navail);
    const int coff = lane * 4;

    float4 acc = make_float4(0.f, 0.f, 0.f, 0.f);
    int  cur   = srow[ws];
    bool first = true;

    for (int i = ws; i < we; i += 4) {
        const int cnt = we - i;
        float4 v[4];
#pragma unroll
        for (int j = 0; j < 4; j++)
            if (j < cnt)
                v[j] = *reinterpret_cast<const float4*>(femb + scol[i + j] * OUT_FEAT + coff);
#pragma unroll
        for (int j = 0; j < 4; j++) {
            if (j < cnt) {
                int r = srow[i + j];
                if (r != cur) {
                    float* xp = x + cur * OUT_FEAT + coff;
                    if (first) {
                        atomicAdd(xp + 0, acc.x); atomicAdd(xp + 1, acc.y);
                        atomicAdd(xp + 2, acc.z); atomicAdd(xp + 3, acc.w);
                        first = false;
                    } else {
                        *reinterpret_cast<float4*>(xp) = acc;
                    }
                    acc = make_float4(0.f, 0.f, 0.f, 0.f);
                    cur = r;
                }
                float ev = sval[i + j];
                acc.x += ev * v[j].x;
                acc.y += ev * v[j].y;
                acc.z += ev * v[j].z;
                acc.w += ev * v[j].w;
            }
        }
    }
    float* xp = x + cur * OUT_FEAT + coff;
    atomicAdd(xp + 0, acc.x); atomicAdd(xp + 1, acc.y);
    atomicAdd(xp + 2, acc.z); atomicAdd(xp + 3, acc.w);
}

// ---------------------------------------------------------------------------
// Launch
// ---------------------------------------------------------------------------
extern "C" void kernel_launch(void* const* d_in, const int* in_sizes, int n_in,
                              void* d_out, int out_size)
{
    const float* feat = (const float*)d_in[0];   // [N, 256]
    const int*   erow = (const int*)  d_in[1];   // [E]
    const int*   ecol = (const int*)  d_in[2];   // [E]
    const float* eval = (const float*)d_in[3];   // [E]
    const float* W    = (const float*)d_in[4];   // [256, 128]

    const int M = in_sizes[0] / IN_FEAT;         // 100000
    const int E = in_sizes[1];                   // 3200000

    float* femb = (float*)d_out;
    float* x    = femb + (size_t)M * OUT_FEAT;

    cudaMemsetAsync(x, 0, (size_t)M * OUT_FEAT * sizeof(float), 0);

    bconv_kernel<<<(IN_FEAT * OUT_FEAT + 255) / 256, 256>>>(W);
    gemm_mma_kernel<<<(M + 127) / 128, 256>>>(feat, femb, M);
    spmm_kernel<<<(E + SP_BCHUNK - 1) / SP_BCHUNK, SP_THREADS>>>(erow, ecol, eval, femb, x, E);
}